// round 16
// baseline (speedup 1.0000x reference)
#include <cuda_runtime.h>
#include <cstdint>

#define N_NODES 100000
#define E_EDGES 800000
#define GRID    148
#define TPB     1024
#define NWARP   (TPB / 32)
#define GSTR    (GRID * TPB)
#define TOTWARPS (GRID * NWARP)

// Scratch (device globals). The fused kernel zeroes its own accumulators
// inside EVERY launch; pure function of inputs (mod atomic fp ordering).
__device__ float g_agg1[N_NODES * 64];
__device__ float g_h   [N_NODES * 128];
__device__ float g_agg2[N_NODES * 128];

// Software grid barrier (grid == #SMs, 1 CTA/SM -> all co-resident).
__device__ unsigned g_bar_arrive;
__device__ unsigned g_bar_gen;

__device__ __forceinline__ void grid_barrier() {
    __syncthreads();
    if (threadIdx.x == 0) {
        __threadfence();
        unsigned gen = atomicAdd(&g_bar_gen, 0u);
        unsigned ticket = atomicAdd(&g_bar_arrive, 1u);
        if (ticket == GRID - 1) {
            atomicExch(&g_bar_arrive, 0u);
            __threadfence();
            atomicAdd(&g_bar_gen, 1u);
        } else {
            while (atomicAdd(&g_bar_gen, 0u) == gen) { __nanosleep(64); }
        }
        __threadfence();
    }
    __syncthreads();
}

__device__ __forceinline__ float eluf(float v) {
    return v > 0.f ? v : expm1f(v);
}

__device__ __forceinline__ uint32_t f2tf32(float f) {
    uint32_t u;
    asm("cvt.rna.tf32.f32 %0, %1;" : "=r"(u) : "f"(f));
    return u;
}

__device__ __forceinline__ void mma_tf32(float c[4], uint32_t a0, uint32_t a1,
                                         uint32_t a2, uint32_t a3,
                                         uint32_t b0, uint32_t b1) {
    asm volatile(
        "mma.sync.aligned.m16n8k8.row.col.f32.tf32.tf32.f32 "
        "{%0,%1,%2,%3}, {%4,%5,%6,%7}, {%8,%9}, {%0,%1,%2,%3};\n"
        : "+f"(c[0]), "+f"(c[1]), "+f"(c[2]), "+f"(c[3])
        : "r"(a0), "r"(a1), "r"(a2), "r"(a3), "r"(b0), "r"(b1));
}

__device__ __forceinline__ void red_v4(float* p, float4 v) {
    asm volatile("red.global.add.v4.f32 [%0], {%1,%2,%3,%4};"
                 :: "l"(p), "f"(v.x), "f"(v.y), "f"(v.z), "f"(v.w)
                 : "memory");
}

// ---------------------------------------------------------------------------
// Scatter 128-feature rows: warp = edge row (512B), 4 edges/iter, int4 index
// loads with one-iteration prefetch (idx latency off the critical path).
// ---------------------------------------------------------------------------
template <bool FEAT_CG>
__device__ void scatter128_phase(const float* __restrict__ feat,
                                 const int* __restrict__ ei,
                                 float* __restrict__ agg) {
    const int lane = threadIdx.x & 31;
    const int gwarp = blockIdx.x * NWARP + (threadIdx.x >> 5);
    const float4* f4 = (const float4*)feat;
    const int STR = TOTWARPS * 4;

    int e0 = gwarp * 4;
    if (e0 >= E_EDGES) return;
    int4 s = *(const int4*)(ei + e0);
    int4 d = *(const int4*)(ei + E_EDGES + e0);
    while (e0 < E_EDGES) {
        int e1 = e0 + STR;
        int ep = (e1 < E_EDGES) ? e1 : 0;          // clamped prefetch addr
        int4 sn = *(const int4*)(ei + ep);
        int4 dn = *(const int4*)(ei + E_EDGES + ep);
        const float4* p0 = f4 + (long long)s.x * 32 + lane;
        const float4* p1 = f4 + (long long)s.y * 32 + lane;
        const float4* p2 = f4 + (long long)s.z * 32 + lane;
        const float4* p3 = f4 + (long long)s.w * 32 + lane;
        float4 v0 = FEAT_CG ? __ldcg(p0) : __ldg(p0);
        float4 v1 = FEAT_CG ? __ldcg(p1) : __ldg(p1);
        float4 v2 = FEAT_CG ? __ldcg(p2) : __ldg(p2);
        float4 v3 = FEAT_CG ? __ldcg(p3) : __ldg(p3);
        red_v4(agg + ((long long)d.x * 32 + lane) * 4, v0);
        red_v4(agg + ((long long)d.y * 32 + lane) * 4, v1);
        red_v4(agg + ((long long)d.z * 32 + lane) * 4, v2);
        red_v4(agg + ((long long)d.w * 32 + lane) * 4, v3);
        e0 = e1; s = sn; d = dn;
    }
}

// ---------------------------------------------------------------------------
// Scatter 64-feature rows: half-warp = edge row (256B); each half-warp owns
// 4 CONTIGUOUS edges (int4 index loads), prefetched one iteration ahead.
// ---------------------------------------------------------------------------
template <bool FEAT_CG>
__device__ void scatter64_phase(const float* __restrict__ feat,
                                const int* __restrict__ ei,
                                float* __restrict__ agg) {
    const int lane = threadIdx.x & 31;
    const int c    = lane & 15;        // float4 index within row
    const int sub  = lane >> 4;        // which half-warp
    const int gwarp = blockIdx.x * NWARP + (threadIdx.x >> 5);
    const float4* f4 = (const float4*)feat;
    const int STR = TOTWARPS * 8;

    int e0 = gwarp * 8 + sub * 4;
    if (e0 >= E_EDGES) return;
    int4 s = *(const int4*)(ei + e0);
    int4 d = *(const int4*)(ei + E_EDGES + e0);
    while (e0 < E_EDGES) {
        int e1 = e0 + STR;
        int ep = (e1 < E_EDGES) ? e1 : 0;
        int4 sn = *(const int4*)(ei + ep);
        int4 dn = *(const int4*)(ei + E_EDGES + ep);
        const float4* p0 = f4 + (long long)s.x * 16 + c;
        const float4* p1 = f4 + (long long)s.y * 16 + c;
        const float4* p2 = f4 + (long long)s.z * 16 + c;
        const float4* p3 = f4 + (long long)s.w * 16 + c;
        float4 v0 = FEAT_CG ? __ldcg(p0) : __ldg(p0);
        float4 v1 = FEAT_CG ? __ldcg(p1) : __ldg(p1);
        float4 v2 = FEAT_CG ? __ldcg(p2) : __ldg(p2);
        float4 v3 = FEAT_CG ? __ldcg(p3) : __ldg(p3);
        red_v4(agg + ((long long)d.x * 16 + c) * 4, v0);
        red_v4(agg + ((long long)d.y * 16 + c) * 4, v1);
        red_v4(agg + ((long long)d.z * 16 + c) * 4, v2);
        red_v4(agg + ((long long)d.w * 16 + c) * 4, v3);
        e0 = e1; s = sn; d = dn;
    }
}

// ---------------------------------------------------------------------------
// TF32 tensor-core GEMM phase (+ optional fused FC head):
//   out[node,128] = [A_row ; B_row] @ [Wrel ; Wroot]^T + bias  (opt. ELU)
// Tile = 64 nodes x 128 outs; 32 warps in 4x8 grid of m16n16 warp-tiles.
// If FUSE_FC: the h2 tile stays in smem; the block computes the FC head
// (relu(h2 @ Wfc1^T + b1) @ Wfc2^T + b2) and writes out[node] directly.
// ---------------------------------------------------------------------------
template <int K, bool DO_ELU, bool A_CG, bool B_CG, bool FUSE_FC>
__device__ void gemm_mma_phase(const float* __restrict__ A,
                               const float* __restrict__ B,
                               const float* __restrict__ Wrel,
                               const float* __restrict__ Wroot,
                               const float* __restrict__ bias,
                               float* __restrict__ out,
                               const float* __restrict__ Wfc1,
                               const float* __restrict__ bfc1,
                               const float* __restrict__ Wfc2,
                               const float* __restrict__ bfc2,
                               float* sm) {
    constexpr int HALF = K / 2;
    constexpr int WROW = 136;       // padded weight row (floats)
    constexpr int SROW = K + 4;     // padded staging row (floats)
    uint32_t* Wt = (uint32_t*)sm;                // [K][WROW] tf32
    uint32_t* S  = (uint32_t*)(sm + K * WROW);   // [64][SROW] tf32
    float* h2s = (float*)S;                      // FUSE_FC: reuse as [64][132]
    float* W1s = sm + K * WROW + 64 * SROW;      // FUSE_FC: 20*128
    float* b1s = W1s + 2560;                     // 20
    float* W2s = b1s + 20;                       // 20

    for (int idx = threadIdx.x; idx < (K / 4) * 128; idx += TPB) {
        int i4 = idx % (K / 4);
        int j  = idx / (K / 4);
        int k0 = i4 * 4;
        float4 v = (k0 < HALF)
            ? *(const float4*)(Wrel  + j * HALF + k0)
            : *(const float4*)(Wroot + j * HALF + (k0 - HALF));
        Wt[(k0 + 0) * WROW + j] = f2tf32(v.x);
        Wt[(k0 + 1) * WROW + j] = f2tf32(v.y);
        Wt[(k0 + 2) * WROW + j] = f2tf32(v.z);
        Wt[(k0 + 3) * WROW + j] = f2tf32(v.w);
    }
    if (FUSE_FC) {
        for (int i = threadIdx.x; i < 2560; i += TPB) W1s[i] = Wfc1[i];
        if (threadIdx.x < 20) {
            b1s[threadIdx.x] = bfc1[threadIdx.x];
            W2s[threadIdx.x] = Wfc2[threadIdx.x];
        }
    }

    const int lane = threadIdx.x & 31;
    const int warp = threadIdx.x >> 5;
    const int mw = warp >> 3;       // 0..3 : node-row group (16 rows each)
    const int nw = warp & 7;        // 0..7 : output-col group (16 cols each)
    const int g  = lane >> 2;       // groupID 0..7
    const int tg = lane & 3;        // threadID_in_group 0..3

    for (int tile = blockIdx.x * 64; tile < N_NODES; tile += GRID * 64) {
        __syncthreads();   // prior iter's S reads done; weights ready (1st)
        for (int idx = threadIdx.x; idx < 64 * (K / 4); idx += TPB) {
            int k4 = idx % (K / 4);
            int nl = idx / (K / 4);
            int node = tile + nl;
            float4 v = make_float4(0.f, 0.f, 0.f, 0.f);
            if (node < N_NODES) {
                if (k4 < HALF / 4) {
                    const float4* ap = ((const float4*)A) + (long long)node * (HALF / 4) + k4;
                    v = A_CG ? __ldcg(ap) : __ldg(ap);
                } else {
                    const float4* bp = ((const float4*)B) + (long long)node * (HALF / 4) + (k4 - HALF / 4);
                    v = B_CG ? __ldcg(bp) : __ldg(bp);
                }
            }
            uint4 t;
            t.x = f2tf32(v.x); t.y = f2tf32(v.y);
            t.z = f2tf32(v.z); t.w = f2tf32(v.w);
            *(uint4*)&S[nl * SROW + k4 * 4] = t;
        }
        __syncthreads();

        float c[2][4] = {};
        const int arow0 = (mw * 16 + g) * SROW;
        const int arow8 = arow0 + 8 * SROW;
        #pragma unroll 4
        for (int kk = 0; kk < K; kk += 8) {
            uint32_t a0 = S[arow0 + kk + tg];
            uint32_t a1 = S[arow8 + kk + tg];
            uint32_t a2 = S[arow0 + kk + tg + 4];
            uint32_t a3 = S[arow8 + kk + tg + 4];
            #pragma unroll
            for (int j = 0; j < 2; j++) {
                int n0 = nw * 16 + j * 8 + g;
                uint32_t b0 = Wt[(kk + tg) * WROW + n0];
                uint32_t b1 = Wt[(kk + 4 + tg) * WROW + n0];
                mma_tf32(c[j], a0, a1, a2, a3, b0, b1);
            }
        }

        if (!FUSE_FC) {
            int r0 = tile + mw * 16 + g;
            int r1 = r0 + 8;
            #pragma unroll
            for (int j = 0; j < 2; j++) {
                int col = nw * 16 + j * 8 + tg * 2;
                float bx = __ldg(bias + col);
                float by = __ldg(bias + col + 1);
                if (r0 < N_NODES) {
                    float ox = c[j][0] + bx, oy = c[j][1] + by;
                    if (DO_ELU) { ox = eluf(ox); oy = eluf(oy); }
                    *(float2*)&out[(long long)r0 * 128 + col] = make_float2(ox, oy);
                }
                if (r1 < N_NODES) {
                    float ox = c[j][2] + bx, oy = c[j][3] + by;
                    if (DO_ELU) { ox = eluf(ox); oy = eluf(oy); }
                    *(float2*)&out[(long long)r1 * 128 + col] = make_float2(ox, oy);
                }
            }
        } else {
            // ---- write h2 tile to smem, then FC head, out[node] direct ----
            __syncthreads();   // all warps done reading S (A-frags)
            int r0l = mw * 16 + g;
            int r1l = r0l + 8;
            #pragma unroll
            for (int j = 0; j < 2; j++) {
                int col = nw * 16 + j * 8 + tg * 2;
                float bx = __ldg(bias + col);
                float by = __ldg(bias + col + 1);
                *(float2*)&h2s[r0l * 132 + col] = make_float2(c[j][0] + bx, c[j][1] + by);
                *(float2*)&h2s[r1l * 132 + col] = make_float2(c[j][2] + bx, c[j][3] + by);
            }
            __syncthreads();

            int grp = threadIdx.x >> 4;      // local node 0..63
            int it  = threadIdx.x & 15;      // 16 threads per node
            int node = tile + grp;
            float acc[20];
            #pragma unroll
            for (int k = 0; k < 20; k++) acc[k] = 0.f;
            const float* hr = &h2s[grp * 132 + it * 8];
            #pragma unroll
            for (int i = 0; i < 8; i++) {
                float v = hr[i];
                const float* w = &W1s[it * 8 + i];
                #pragma unroll
                for (int k = 0; k < 20; k++) acc[k] += v * w[k * 128];
            }
            #pragma unroll
            for (int off = 8; off >= 1; off >>= 1) {
                #pragma unroll
                for (int k = 0; k < 20; k++)
                    acc[k] += __shfl_down_sync(0xffffffffu, acc[k], off, 16);
            }
            if (it == 0 && node < N_NODES) {
                float o = __ldg(bfc2);
                #pragma unroll
                for (int k = 0; k < 20; k++)
                    o += fmaxf(acc[k] + b1s[k], 0.f) * W2s[k];
                out[node] = o;
            }
        }
    }
    __syncthreads();
}

// ---------------------------------------------------------------------------
// Single fused kernel: the entire network, one launch, pure function of inputs.
// ---------------------------------------------------------------------------
__global__ void __launch_bounds__(TPB, 1)
fused_gcn(const float* __restrict__ x, const int* __restrict__ ei,
          const float* __restrict__ W1_rel, const float* __restrict__ b1,
          const float* __restrict__ W1_root,
          const float* __restrict__ W2_rel, const float* __restrict__ b2,
          const float* __restrict__ W2_root,
          const float* __restrict__ Wfc1, const float* __restrict__ bfc1,
          const float* __restrict__ Wfc2, const float* __restrict__ bfc2,
          float* __restrict__ out) {
    extern __shared__ float sm[];
    const int gtid = blockIdx.x * TPB + threadIdx.x;
    const float4 z = make_float4(0.f, 0.f, 0.f, 0.f);

    // Phase 0: zero agg1 (must precede scatter64's reductions)
    {
        float4* a1 = (float4*)g_agg1;
        for (int i = gtid; i < N_NODES * 64 / 4; i += GSTR) a1[i] = z;
    }
    grid_barrier();

    // Phase 1: agg1[dst] += x[src]; also zero agg2 (independent, overlaps)
    scatter64_phase<false>(x, ei, g_agg1);
    {
        float4* a2 = (float4*)g_agg2;
        for (int i = gtid; i < N_NODES * 128 / 4; i += GSTR) a2[i] = z;
    }
    grid_barrier();

    // Phase 2: h = elu(agg1 @ W1_rel^T + b1 + x @ W1_root^T)  [TF32 mma]
    gemm_mma_phase<128, true, true, false, false>(
        g_agg1, x, W1_rel, W1_root, b1, g_h,
        nullptr, nullptr, nullptr, nullptr, sm);
    grid_barrier();

    // Phase 3: agg2[dst] += h[src]
    scatter128_phase<true>(g_h, ei, g_agg2);
    grid_barrier();

    // Phase 4: h2 = agg2 @ W2_rel^T + b2 + h @ W2_root^T, then fused FC head
    //          out[n] = relu(h2 @ Wfc1^T + bfc1) @ Wfc2^T + bfc2
    gemm_mma_phase<256, false, true, true, true>(
        g_agg2, g_h, W2_rel, W2_root, b2, out,
        Wfc1, bfc1, Wfc2, bfc2, sm);
}

// ---------------------------------------------------------------------------
extern "C" void kernel_launch(void* const* d_in, const int* in_sizes, int n_in,
                              void* d_out, int out_size) {
    const float* x       = (const float*)d_in[0];
    const int*   ei      = (const int*)d_in[1];
    const float* W1_rel  = (const float*)d_in[2];
    const float* b1      = (const float*)d_in[3];
    const float* W1_root = (const float*)d_in[4];
    const float* W2_rel  = (const float*)d_in[5];
    const float* b2      = (const float*)d_in[6];
    const float* W2_root = (const float*)d_in[7];
    const float* Wfc1    = (const float*)d_in[8];
    const float* bfc1    = (const float*)d_in[9];
    const float* Wfc2    = (const float*)d_in[10];
    const float* bfc2    = (const float*)d_in[11];
    float* out = (float*)d_out;

    // smem: K=256 phase: 256*136 + 64*260 + (2560+20+20+pad) floats = 216240 B
    const int smem = (256 * 136 + 64 * 260 + 2604) * 4;
    cudaFuncSetAttribute(fused_gcn,
                         cudaFuncAttributeMaxDynamicSharedMemorySize, smem);

    fused_gcn<<<GRID, TPB, smem>>>(x, ei, W1_rel, b1, W1_root,
                                   W2_rel, b2, W2_root,
                                   Wfc1, bfc1, Wfc2, bfc2, out);
}

// round 17
// speedup vs baseline: 1.0208x; 1.0208x over previous
#include <cuda_runtime.h>
#include <cstdint>

#define N_NODES 100000
#define E_EDGES 800000
#define GRID    148
#define TPB     1024
#define NWARP   (TPB / 32)
#define GSTR    (GRID * TPB)
#define TOTWARPS (GRID * NWARP)
#define CHUNK   676              // ceil(N_NODES / GRID)

// Scratch (device globals). Everything is rebuilt inside EVERY launch;
// kernel is a pure function of inputs (mod fp sum-order from the CSR fill).
__device__ float g_agg1[N_NODES * 64];
__device__ float g_h   [N_NODES * 128];
__device__ float g_agg2[N_NODES * 128];
__device__ int   g_deg [N_NODES];
__device__ int   g_rowptr[N_NODES + 1];
__device__ int   g_pos [N_NODES];
__device__ int   g_eidx[E_EDGES];
__device__ int   g_partial[GRID];

// Software grid barrier (grid == #SMs, 1 CTA/SM -> all co-resident).
__device__ unsigned g_bar_arrive;
__device__ unsigned g_bar_gen;

__device__ __forceinline__ void grid_barrier() {
    __syncthreads();
    if (threadIdx.x == 0) {
        __threadfence();
        unsigned gen = atomicAdd(&g_bar_gen, 0u);
        unsigned ticket = atomicAdd(&g_bar_arrive, 1u);
        if (ticket == GRID - 1) {
            atomicExch(&g_bar_arrive, 0u);
            __threadfence();
            atomicAdd(&g_bar_gen, 1u);
        } else {
            while (atomicAdd(&g_bar_gen, 0u) == gen) { __nanosleep(64); }
        }
        __threadfence();
    }
    __syncthreads();
}

__device__ __forceinline__ float eluf(float v) {
    return v > 0.f ? v : expm1f(v);
}

__device__ __forceinline__ uint32_t f2tf32(float f) {
    uint32_t u;
    asm("cvt.rna.tf32.f32 %0, %1;" : "=r"(u) : "f"(f));
    return u;
}

__device__ __forceinline__ void mma_tf32(float c[4], uint32_t a0, uint32_t a1,
                                         uint32_t a2, uint32_t a3,
                                         uint32_t b0, uint32_t b1) {
    asm volatile(
        "mma.sync.aligned.m16n8k8.row.col.f32.tf32.tf32.f32 "
        "{%0,%1,%2,%3}, {%4,%5,%6,%7}, {%8,%9}, {%0,%1,%2,%3};\n"
        : "+f"(c[0]), "+f"(c[1]), "+f"(c[2]), "+f"(c[3])
        : "r"(a0), "r"(a1), "r"(a2), "r"(a3), "r"(b0), "r"(b1));
}

// ---------------------------------------------------------------------------
// CSR gather-sum, 128-feature rows: warp = one dst node; lane = one float4
// column. 4 edges batched per inner iteration (4 gathers in flight).
// ---------------------------------------------------------------------------
__device__ void gather128_phase(const float* __restrict__ feat,
                                float* __restrict__ agg) {
    const int lane = threadIdx.x & 31;
    const int gwarp = blockIdx.x * NWARP + (threadIdx.x >> 5);
    const float4* f4 = (const float4*)feat;

    for (int node = gwarp; node < N_NODES; node += TOTWARPS) {
        int beg = __ldcg(&g_rowptr[node]);
        int end = __ldcg(&g_rowptr[node + 1]);
        float4 acc = make_float4(0.f, 0.f, 0.f, 0.f);
        int j = beg;
        for (; j + 4 <= end; j += 4) {
            int s0 = __ldcg(&g_eidx[j + 0]);
            int s1 = __ldcg(&g_eidx[j + 1]);
            int s2 = __ldcg(&g_eidx[j + 2]);
            int s3 = __ldcg(&g_eidx[j + 3]);
            float4 v0 = __ldcg(f4 + (long long)s0 * 32 + lane);
            float4 v1 = __ldcg(f4 + (long long)s1 * 32 + lane);
            float4 v2 = __ldcg(f4 + (long long)s2 * 32 + lane);
            float4 v3 = __ldcg(f4 + (long long)s3 * 32 + lane);
            acc.x += (v0.x + v1.x) + (v2.x + v3.x);
            acc.y += (v0.y + v1.y) + (v2.y + v3.y);
            acc.z += (v0.z + v1.z) + (v2.z + v3.z);
            acc.w += (v0.w + v1.w) + (v2.w + v3.w);
        }
        for (; j < end; j++) {
            int s = __ldcg(&g_eidx[j]);
            float4 v = __ldcg(f4 + (long long)s * 32 + lane);
            acc.x += v.x; acc.y += v.y; acc.z += v.z; acc.w += v.w;
        }
        ((float4*)agg)[(long long)node * 32 + lane] = acc;
    }
}

// ---------------------------------------------------------------------------
// CSR gather-sum, 64-feature rows: half-warp = one dst node.
// ---------------------------------------------------------------------------
__device__ void gather64_phase(const float* __restrict__ feat,
                               float* __restrict__ agg) {
    const int lane = threadIdx.x & 31;
    const int c    = lane & 15;
    const int sub  = lane >> 4;
    const int ghw  = (blockIdx.x * NWARP + (threadIdx.x >> 5)) * 2 + sub;
    const float4* f4 = (const float4*)feat;

    for (int node = ghw; node < N_NODES; node += TOTWARPS * 2) {
        int beg = __ldcg(&g_rowptr[node]);
        int end = __ldcg(&g_rowptr[node + 1]);
        float4 acc = make_float4(0.f, 0.f, 0.f, 0.f);
        int j = beg;
        for (; j + 4 <= end; j += 4) {
            int s0 = __ldcg(&g_eidx[j + 0]);
            int s1 = __ldcg(&g_eidx[j + 1]);
            int s2 = __ldcg(&g_eidx[j + 2]);
            int s3 = __ldcg(&g_eidx[j + 3]);
            float4 v0 = __ldg(f4 + (long long)s0 * 16 + c);
            float4 v1 = __ldg(f4 + (long long)s1 * 16 + c);
            float4 v2 = __ldg(f4 + (long long)s2 * 16 + c);
            float4 v3 = __ldg(f4 + (long long)s3 * 16 + c);
            acc.x += (v0.x + v1.x) + (v2.x + v3.x);
            acc.y += (v0.y + v1.y) + (v2.y + v3.y);
            acc.z += (v0.z + v1.z) + (v2.z + v3.z);
            acc.w += (v0.w + v1.w) + (v2.w + v3.w);
        }
        for (; j < end; j++) {
            int s = __ldcg(&g_eidx[j]);
            float4 v = __ldg(f4 + (long long)s * 16 + c);
            acc.x += v.x; acc.y += v.y; acc.z += v.z; acc.w += v.w;
        }
        ((float4*)agg)[(long long)node * 16 + c] = acc;
    }
}

// ---------------------------------------------------------------------------
// TF32 tensor-core GEMM phase (+ optional fused FC head). Unchanged from R15.
// ---------------------------------------------------------------------------
template <int K, bool DO_ELU, bool FUSE_FC>
__device__ void gemm_mma_phase(const float* __restrict__ A,
                               const float* __restrict__ B,
                               const float* __restrict__ Wrel,
                               const float* __restrict__ Wroot,
                               const float* __restrict__ bias,
                               float* __restrict__ out,
                               const float* __restrict__ Wfc1,
                               const float* __restrict__ bfc1,
                               const float* __restrict__ Wfc2,
                               const float* __restrict__ bfc2,
                               float* sm) {
    constexpr int HALF = K / 2;
    constexpr int WROW = 136;
    constexpr int SROW = K + 4;
    uint32_t* Wt = (uint32_t*)sm;                // [K][WROW] tf32
    uint32_t* S  = (uint32_t*)(sm + K * WROW);   // [64][SROW] tf32
    float* h2s = (float*)S;                      // FUSE_FC: reuse as [64][132]
    float* W1s = sm + K * WROW + 64 * SROW;      // FUSE_FC: 20*128
    float* b1s = W1s + 2560;
    float* W2s = b1s + 20;

    for (int idx = threadIdx.x; idx < (K / 4) * 128; idx += TPB) {
        int i4 = idx % (K / 4);
        int j  = idx / (K / 4);
        int k0 = i4 * 4;
        float4 v = (k0 < HALF)
            ? *(const float4*)(Wrel  + j * HALF + k0)
            : *(const float4*)(Wroot + j * HALF + (k0 - HALF));
        Wt[(k0 + 0) * WROW + j] = f2tf32(v.x);
        Wt[(k0 + 1) * WROW + j] = f2tf32(v.y);
        Wt[(k0 + 2) * WROW + j] = f2tf32(v.z);
        Wt[(k0 + 3) * WROW + j] = f2tf32(v.w);
    }
    if (FUSE_FC) {
        for (int i = threadIdx.x; i < 2560; i += TPB) W1s[i] = Wfc1[i];
        if (threadIdx.x < 20) {
            b1s[threadIdx.x] = bfc1[threadIdx.x];
            W2s[threadIdx.x] = Wfc2[threadIdx.x];
        }
    }

    const int lane = threadIdx.x & 31;
    const int warp = threadIdx.x >> 5;
    const int mw = warp >> 3;
    const int nw = warp & 7;
    const int g  = lane >> 2;
    const int tg = lane & 3;

    for (int tile = blockIdx.x * 64; tile < N_NODES; tile += GRID * 64) {
        __syncthreads();
        for (int idx = threadIdx.x; idx < 64 * (K / 4); idx += TPB) {
            int k4 = idx % (K / 4);
            int nl = idx / (K / 4);
            int node = tile + nl;
            float4 v = make_float4(0.f, 0.f, 0.f, 0.f);
            if (node < N_NODES) {
                if (k4 < HALF / 4) {
                    v = __ldcg(((const float4*)A) + (long long)node * (HALF / 4) + k4);
                } else {
                    v = __ldcg(((const float4*)B) + (long long)node * (HALF / 4) + (k4 - HALF / 4));
                }
            }
            uint4 t;
            t.x = f2tf32(v.x); t.y = f2tf32(v.y);
            t.z = f2tf32(v.z); t.w = f2tf32(v.w);
            *(uint4*)&S[nl * SROW + k4 * 4] = t;
        }
        __syncthreads();

        float c[2][4] = {};
        const int arow0 = (mw * 16 + g) * SROW;
        const int arow8 = arow0 + 8 * SROW;
        #pragma unroll 4
        for (int kk = 0; kk < K; kk += 8) {
            uint32_t a0 = S[arow0 + kk + tg];
            uint32_t a1 = S[arow8 + kk + tg];
            uint32_t a2 = S[arow0 + kk + tg + 4];
            uint32_t a3 = S[arow8 + kk + tg + 4];
            #pragma unroll
            for (int j = 0; j < 2; j++) {
                int n0 = nw * 16 + j * 8 + g;
                uint32_t b0 = Wt[(kk + tg) * WROW + n0];
                uint32_t b1 = Wt[(kk + 4 + tg) * WROW + n0];
                mma_tf32(c[j], a0, a1, a2, a3, b0, b1);
            }
        }

        if (!FUSE_FC) {
            int r0 = tile + mw * 16 + g;
            int r1 = r0 + 8;
            #pragma unroll
            for (int j = 0; j < 2; j++) {
                int col = nw * 16 + j * 8 + tg * 2;
                float bx = __ldg(bias + col);
                float by = __ldg(bias + col + 1);
                if (r0 < N_NODES) {
                    float ox = c[j][0] + bx, oy = c[j][1] + by;
                    if (DO_ELU) { ox = eluf(ox); oy = eluf(oy); }
                    *(float2*)&out[(long long)r0 * 128 + col] = make_float2(ox, oy);
                }
                if (r1 < N_NODES) {
                    float ox = c[j][2] + bx, oy = c[j][3] + by;
                    if (DO_ELU) { ox = eluf(ox); oy = eluf(oy); }
                    *(float2*)&out[(long long)r1 * 128 + col] = make_float2(ox, oy);
                }
            }
        } else {
            __syncthreads();
            int r0l = mw * 16 + g;
            int r1l = r0l + 8;
            #pragma unroll
            for (int j = 0; j < 2; j++) {
                int col = nw * 16 + j * 8 + tg * 2;
                float bx = __ldg(bias + col);
                float by = __ldg(bias + col + 1);
                *(float2*)&h2s[r0l * 132 + col] = make_float2(c[j][0] + bx, c[j][1] + by);
                *(float2*)&h2s[r1l * 132 + col] = make_float2(c[j][2] + bx, c[j][3] + by);
            }
            __syncthreads();

            int grp = threadIdx.x >> 4;
            int it  = threadIdx.x & 15;
            int node = tile + grp;
            float acc[20];
            #pragma unroll
            for (int k = 0; k < 20; k++) acc[k] = 0.f;
            const float* hr = &h2s[grp * 132 + it * 8];
            #pragma unroll
            for (int i = 0; i < 8; i++) {
                float v = hr[i];
                const float* w = &W1s[it * 8 + i];
                #pragma unroll
                for (int k = 0; k < 20; k++) acc[k] += v * w[k * 128];
            }
            #pragma unroll
            for (int off = 8; off >= 1; off >>= 1) {
                #pragma unroll
                for (int k = 0; k < 20; k++)
                    acc[k] += __shfl_down_sync(0xffffffffu, acc[k], off, 16);
            }
            if (it == 0 && node < N_NODES) {
                float o = __ldg(bfc2);
                #pragma unroll
                for (int k = 0; k < 20; k++)
                    o += fmaxf(acc[k] + b1s[k], 0.f) * W2s[k];
                out[node] = o;
            }
        }
    }
    __syncthreads();
}

// ---------------------------------------------------------------------------
// Single fused kernel.
// ---------------------------------------------------------------------------
__global__ void __launch_bounds__(TPB, 1)
fused_gcn(const float* __restrict__ x, const int* __restrict__ ei,
          const float* __restrict__ W1_rel, const float* __restrict__ b1,
          const float* __restrict__ W1_root,
          const float* __restrict__ W2_rel, const float* __restrict__ b2,
          const float* __restrict__ W2_root,
          const float* __restrict__ Wfc1, const float* __restrict__ bfc1,
          const float* __restrict__ Wfc2, const float* __restrict__ bfc2,
          float* __restrict__ out) {
    extern __shared__ float sm[];
    const int gtid = blockIdx.x * TPB + threadIdx.x;
    const int t = threadIdx.x;
    const int base = blockIdx.x * CHUNK;

    // ---- CSR build (once per launch; serves both aggregations) ----
    // Phase 0: zero degree counters
    for (int i = gtid; i < N_NODES; i += GSTR) g_deg[i] = 0;
    grid_barrier();

    // Phase 1: degree histogram
    for (int e = gtid; e < E_EDGES; e += GSTR)
        atomicAdd(&g_deg[__ldg(ei + E_EDGES + e)], 1);
    grid_barrier();

    // Phase 2a: block-local inclusive scan of this block's CHUNK of degrees
    int* ssc = (int*)sm;
    {
        int v = 0;
        if (t < CHUNK && base + t < N_NODES) v = g_deg[base + t];
        ssc[t] = v;
        __syncthreads();
        for (int off = 1; off < TPB; off <<= 1) {
            int u = (t >= off) ? ssc[t - off] : 0;
            __syncthreads();
            ssc[t] += u;
            __syncthreads();
        }
        if (t == TPB - 1) g_partial[blockIdx.x] = ssc[TPB - 1];
    }
    grid_barrier();

    // Phase 2b: scan the per-block totals (cheap serial, block 0)
    if (blockIdx.x == 0 && t == 0) {
        int acc = 0;
        for (int b = 0; b < GRID; b++) {
            int v = g_partial[b];
            g_partial[b] = acc;
            acc += v;
        }
        g_rowptr[N_NODES] = acc;   // == E_EDGES
    }
    grid_barrier();

    // Phase 2c: write rowptr and fill cursors (smem scan persists across barriers)
    if (t < CHUNK && base + t < N_NODES) {
        int excl = g_partial[blockIdx.x] + ssc[t] - g_deg[base + t];
        g_rowptr[base + t] = excl;
        g_pos[base + t] = excl;
    }
    grid_barrier();

    // Phase 3: fill sorted source-index array
    for (int e = gtid; e < E_EDGES; e += GSTR) {
        int dst = __ldg(ei + E_EDGES + e);
        int slot = atomicAdd(&g_pos[dst], 1);
        g_eidx[slot] = __ldg(ei + e);
    }
    grid_barrier();

    // ---- network ----
    // Phase 4: agg1[n] = sum_{src in N(n)} x[src]   (64 feats)
    gather64_phase(x, g_agg1);
    grid_barrier();

    // Phase 5: h = elu(agg1 @ W1_rel^T + b1 + x @ W1_root^T)
    gemm_mma_phase<128, true, false>(
        g_agg1, x, W1_rel, W1_root, b1, g_h,
        nullptr, nullptr, nullptr, nullptr, sm);
    grid_barrier();

    // Phase 6: agg2[n] = sum_{src in N(n)} h[src]   (128 feats)
    gather128_phase(g_h, g_agg2);
    grid_barrier();

    // Phase 7: h2 = agg2 @ W2_rel^T + b2 + h @ W2_root^T, fused FC head -> out
    gemm_mma_phase<256, false, true>(
        g_agg2, g_h, W2_rel, W2_root, b2, out,
        Wfc1, bfc1, Wfc2, bfc2, sm);
}

// ---------------------------------------------------------------------------
extern "C" void kernel_launch(void* const* d_in, const int* in_sizes, int n_in,
                              void* d_out, int out_size) {
    const float* x       = (const float*)d_in[0];
    const int*   ei      = (const int*)d_in[1];
    const float* W1_rel  = (const float*)d_in[2];
    const float* b1      = (const float*)d_in[3];
    const float* W1_root = (const float*)d_in[4];
    const float* W2_rel  = (const float*)d_in[5];
    const float* b2      = (const float*)d_in[6];
    const float* W2_root = (const float*)d_in[7];
    const float* Wfc1    = (const float*)d_in[8];
    const float* bfc1    = (const float*)d_in[9];
    const float* Wfc2    = (const float*)d_in[10];
    const float* bfc2    = (const float*)d_in[11];
    float* out = (float*)d_out;

    // smem: K=256 phase: 256*136 + 64*260 + (2560+20+20+pad) floats = 216240 B
    const int smem = (256 * 136 + 64 * 260 + 2604) * 4;
    cudaFuncSetAttribute(fused_gcn,
                         cudaFuncAttributeMaxDynamicSharedMemorySize, smem);

    fused_gcn<<<GRID, TPB, smem>>>(x, ei, W1_rel, b1, W1_root,
                                   W2_rel, b2, W2_root,
                                   Wfc1, bfc1, Wfc2, bfc2, out);
}